// round 15
// baseline (speedup 1.0000x reference)
#include <cuda_runtime.h>
#include <cuda_fp16.h>
#include <cstdint>

// ---------------- problem constants ----------------
#define MAXN 100000
#define MAXE 1600000
#define MAXG 512
#define NBLK 444              // 3 blocks per SM (148 SMs): residency guaranteed
#define NTHR 512
#define NWARP 16
#define TOTW (NBLK * NWARP)   // 7104 warps
#define CHUNK 226             // ceil(MAXN / NBLK)

typedef long long i64;

// ---------------- static scratch (device-code references only) -------------
__device__ unsigned d_bar_arrive;
__device__ unsigned d_bar_gen;
__device__ int   d_nz_e;              // set-only: 1 => edge indices are int32
__device__ int   d_nz_b;
__device__ int   d_sel64;
__device__ int   d_sel32;
__device__ int   d_ecnt  [MAXN];
__device__ int   d_rowptr[MAXN + 1];
__device__ int   d_cursor[MAXN];
__device__ int   d_bsum  [NBLK];
__device__ int   d_bsumx [NBLK];
__device__ int   d_srcs  [MAXE];
__device__ float d_dinv  [MAXN];
__device__ __align__(128) float   d_gA [MAXN * 32];
__device__ __align__(128) __half2 d_gBh[MAXN * 32];
__device__ float d_pool[MAXG];
__device__ float d_cnt [MAXG];

// ---------------- helpers ----------------
__device__ __forceinline__ int clampi(int v, int lo, int hi) {
    return min(max(v, lo), hi);
}
__device__ __forceinline__ int ld_idx(const void* p, long long e, int is64) {
    if (is64) return (int)((const i64*)p)[e];
    return ((const int*)p)[e];
}

// Global barrier across NBLK blocks (release fence in, CCTL.IVALL out).
__device__ __forceinline__ void gbar() {
    __syncthreads();
    if (threadIdx.x == 0) {
        __threadfence();
        unsigned gen = atomicAdd(&d_bar_gen, 0u);
        unsigned a   = atomicAdd(&d_bar_arrive, 1u);
        if (a == NBLK - 1) {
            atomicExch(&d_bar_arrive, 0u);
            atomicAdd(&d_bar_gen, 1u);
        } else {
            while (atomicAdd(&d_bar_gen, 0u) == gen) __nanosleep(64);
        }
        __threadfence();
    }
    __syncthreads();
}

// ---------------- the one kernel ----------------
__global__ void __launch_bounds__(NTHR, 3)
k_all(const float* __restrict__ x, const void* __restrict__ ei,
      const void* __restrict__ batch,
      const float* c64a, const float* c64b,
      const float* __restrict__ W2, const float* __restrict__ W3,
      const float* c32a, const float* c32b, const float* c32c,
      const float* __restrict__ bfc, float* __restrict__ out,
      int n, int E, int G) {
    __shared__ float ws[64 * 33];
    __shared__ int   s_w[NWARP];

    const int tid  = threadIdx.x;
    const int lane = tid & 31;
    const int wid  = tid >> 5;
    const int bid  = blockIdx.x;
    const int gtid = bid * NTHR + tid;
    const int GS   = NBLK * NTHR;

    // ---- Phase 0: zero + width detect + weight/bias disambiguation ----
    for (int i = gtid; i < n; i += GS) d_ecnt[i] = 0;
    if (gtid < G) { d_pool[gtid] = 0.0f; d_cnt[gtid] = 0.0f; }
    if (gtid < 4096) {
        if (((const int*)ei)[2 * gtid + 1] != 0) d_nz_e = 1;
    } else if (gtid < 8192) {
        int j = gtid - 4096;
        if (((const int*)batch)[2 * j + 1] != 0) d_nz_b = 1;
    }
    if (bid == 0 && tid < 32) {
        unsigned nz64 = __ballot_sync(0xffffffffu,
                                      c64a[tid] != 0.0f || c64a[tid + 32] != 0.0f);
        unsigned nzA  = __ballot_sync(0xffffffffu, c32a[tid] != 0.0f);
        unsigned nzB  = __ballot_sync(0xffffffffu, c32b[tid] != 0.0f);
        if (tid == 0) {
            d_sel64 = nz64 ? 0 : 1;
            d_sel32 = nzA ? 0 : (nzB ? 1 : 2);
        }
    }
    gbar();

    const int is64e = !d_nz_e;

    // ---- Phase 1: in-degree histogram over dst ----
    for (int e = gtid; e < E; e += GS) {
        int d = clampi(ld_idx(ei, (long long)E + e, is64e), 0, n - 1);
        atomicAdd(&d_ecnt[d], 1);
    }
    gbar();

    // ---- Phase 2a: per-block partial sums over contiguous chunk ----
    const int cbeg = bid * CHUNK;
    const int cend = min(n, cbeg + CHUNK);
    {
        int s = 0;
        for (int i = cbeg + tid; i < cend; i += NTHR) s += d_ecnt[i];
        #pragma unroll
        for (int off = 16; off > 0; off >>= 1)
            s += __shfl_xor_sync(0xffffffffu, s, off);
        if (lane == 0) s_w[wid] = s;
        __syncthreads();
        if (wid == 0) {
            int w = (lane < NWARP) ? s_w[lane] : 0;
            #pragma unroll
            for (int off = 16; off > 0; off >>= 1)
                w += __shfl_xor_sync(0xffffffffu, w, off);
            if (lane == 0) d_bsum[bid] = w;
        }
    }
    gbar();

    // ---- Phase 2b: block 0 exclusive-scans the NBLK partials ----
    if (bid == 0) {
        int v = (tid < NBLK) ? d_bsum[tid] : 0;
        int xx = v;
        #pragma unroll
        for (int off = 1; off < 32; off <<= 1) {
            int t = __shfl_up_sync(0xffffffffu, xx, off);
            if (lane >= off) xx += t;
        }
        if (lane == 31) s_w[wid] = xx;
        __syncthreads();
        if (wid == 0) {
            int w = (lane < NWARP) ? s_w[lane] : 0;
            #pragma unroll
            for (int off = 1; off < NWARP; off <<= 1) {
                int t = __shfl_up_sync(0xffffffffu, w, off);
                if (lane >= off) w += t;
            }
            if (lane < NWARP) s_w[lane] = w;
        }
        __syncthreads();
        int incl = xx + (wid > 0 ? s_w[wid - 1] : 0);
        if (tid < NBLK) d_bsumx[tid] = incl - v;
        if (tid == NBLK - 1) d_rowptr[n] = incl;
        __syncthreads();
    }
    gbar();

    // ---- Phase 2c: local exclusive scan -> rowptr/cursor/dinv; fused L1 ----
    {
        int carry = d_bsumx[bid];
        for (int base = cbeg; base < cend; base += NTHR) {
            int i = base + tid;
            int v = (i < cend) ? d_ecnt[i] : 0;
            int xx = v;
            #pragma unroll
            for (int off = 1; off < 32; off <<= 1) {
                int t = __shfl_up_sync(0xffffffffu, xx, off);
                if (lane >= off) xx += t;
            }
            if (lane == 31) s_w[wid] = xx;
            __syncthreads();
            if (wid == 0) {
                int w = (lane < NWARP) ? s_w[lane] : 0;
                #pragma unroll
                for (int off = 1; off < NWARP; off <<= 1) {
                    int t = __shfl_up_sync(0xffffffffu, w, off);
                    if (lane >= off) w += t;
                }
                if (lane < NWARP) s_w[lane] = w;
            }
            __syncthreads();
            int incl = xx + (wid > 0 ? s_w[wid - 1] : 0);
            int btot = s_w[NWARP - 1];
            if (i < cend) {
                int pre = carry + incl - v;
                d_rowptr[i] = pre;
                d_cursor[i] = pre;
                d_dinv[i]   = rsqrtf(1.0f + (float)v);
            }
            carry += btot;
            __syncthreads();
        }
        const float* W1 = (d_sel64 == 0) ? c64a : c64b;
        int cnt = cend - cbeg;
        for (int t = tid; t < cnt * 32; t += NTHR) {
            int node = cbeg + (t >> 5);
            int f = t & 31;
            float h = W1[f * 2 + 0] * x[node * 2 + 0]
                    + W1[f * 2 + 1] * x[node * 2 + 1];
            d_gA[(size_t)node * 32 + f] = h * d_dinv[node];
        }
    }
    gbar();

    // ---- Phase 3: CSR placement ----
    for (int e = gtid; e < E; e += GS) {
        int s = clampi(ld_idx(ei, e, is64e),                0, n - 1);
        int d = clampi(ld_idx(ei, (long long)E + e, is64e), 0, n - 1);
        int pos = atomicAdd(&d_cursor[d], 1);
        d_srcs[pos] = s;
    }
    gbar();

    const int gw = bid * NWARP + wid;

    // ---- Phase 4: agg1 = Agg(g1)+relu+GEMV W2 -> gBh (half2 pairs) ----
    for (int t = tid; t < 64 * 32; t += NTHR)
        ws[(t >> 5) * 33 + (t & 31)] = W2[t];
    __syncthreads();
    {
        const float* b1 = (d_sel32 == 0) ? c32b : c32a;
        for (int i = gw; i < n; i += TOTW) {
            int beg = d_rowptr[i], end = d_rowptr[i + 1];
            float a0 = d_gA[(size_t)i * 32 + lane], a1 = 0.f, a2 = 0.f, a3 = 0.f;
            int c = beg;
            for (; c + 8 <= end; c += 8) {
                int s0 = d_srcs[c + 0], s1 = d_srcs[c + 1];
                int s2 = d_srcs[c + 2], s3 = d_srcs[c + 3];
                int s4 = d_srcs[c + 4], s5 = d_srcs[c + 5];
                int s6 = d_srcs[c + 6], s7 = d_srcs[c + 7];
                float v0 = d_gA[(size_t)s0 * 32 + lane];
                float v1 = d_gA[(size_t)s1 * 32 + lane];
                float v2 = d_gA[(size_t)s2 * 32 + lane];
                float v3 = d_gA[(size_t)s3 * 32 + lane];
                float v4 = d_gA[(size_t)s4 * 32 + lane];
                float v5 = d_gA[(size_t)s5 * 32 + lane];
                float v6 = d_gA[(size_t)s6 * 32 + lane];
                float v7 = d_gA[(size_t)s7 * 32 + lane];
                a0 += v0 + v4; a1 += v1 + v5; a2 += v2 + v6; a3 += v3 + v7;
            }
            for (; c < end; c++)
                a0 += d_gA[(size_t)d_srcs[c] * 32 + lane];
            float acc = (a0 + a1) + (a2 + a3);
            float dv = d_dinv[i];
            float xi = fmaxf(acc * dv + b1[lane], 0.0f);
            float s0 = 0.0f, s1 = 0.0f;
            #pragma unroll
            for (int k = 0; k < 32; k++) {
                float xk = __shfl_sync(0xffffffffu, xi, k);
                s0 = fmaf(xk, ws[(2 * lane)     * 33 + k], s0);
                s1 = fmaf(xk, ws[(2 * lane + 1) * 33 + k], s1);
            }
            d_gBh[(size_t)i * 32 + lane] = __floats2half2_rn(s0 * dv, s1 * dv);
        }
    }
    gbar();

    // ---- Phase 5: agg2 = Agg(gBh)+relu+GEMV W3 -> gA ----
    for (int t = tid; t < 32 * 64; t += NTHR)
        ws[(t >> 6) * 65 + (t & 63)] = W3[t];
    __syncthreads();
    {
        const float* b2 = (d_sel64 == 0) ? c64b : c64a;
        for (int i = gw; i < n; i += TOTW) {
            float2 self = __half22float2(d_gBh[(size_t)i * 32 + lane]);
            float a0 = self.x, a1 = self.y, a2 = 0.f, a3 = 0.f;
            int beg = d_rowptr[i], end = d_rowptr[i + 1];
            int c = beg;
            for (; c + 8 <= end; c += 8) {
                int s0 = d_srcs[c + 0], s1 = d_srcs[c + 1];
                int s2 = d_srcs[c + 2], s3 = d_srcs[c + 3];
                int s4 = d_srcs[c + 4], s5 = d_srcs[c + 5];
                int s6 = d_srcs[c + 6], s7 = d_srcs[c + 7];
                float2 v0 = __half22float2(d_gBh[(size_t)s0 * 32 + lane]);
                float2 v1 = __half22float2(d_gBh[(size_t)s1 * 32 + lane]);
                float2 v2 = __half22float2(d_gBh[(size_t)s2 * 32 + lane]);
                float2 v3 = __half22float2(d_gBh[(size_t)s3 * 32 + lane]);
                float2 v4 = __half22float2(d_gBh[(size_t)s4 * 32 + lane]);
                float2 v5 = __half22float2(d_gBh[(size_t)s5 * 32 + lane]);
                float2 v6 = __half22float2(d_gBh[(size_t)s6 * 32 + lane]);
                float2 v7 = __half22float2(d_gBh[(size_t)s7 * 32 + lane]);
                a0 += v0.x + v4.x; a1 += v0.y + v4.y;
                a2 += v1.x + v5.x; a3 += v1.y + v5.y;
                a0 += v2.x + v6.x; a1 += v2.y + v6.y;
                a2 += v3.x + v7.x; a3 += v3.y + v7.y;
            }
            for (; c < end; c++) {
                float2 v = __half22float2(d_gBh[(size_t)d_srcs[c] * 32 + lane]);
                a0 += v.x; a1 += v.y;
            }
            float acc0 = a0 + a2, acc1 = a1 + a3;
            float dv = d_dinv[i];
            float xe = fmaxf(acc0 * dv + b2[2 * lane],     0.0f);
            float xo = fmaxf(acc1 * dv + b2[2 * lane + 1], 0.0f);
            float s = 0.0f;
            #pragma unroll
            for (int k = 0; k < 32; k++) {
                float xk0 = __shfl_sync(0xffffffffu, xe, k);
                float xk1 = __shfl_sync(0xffffffffu, xo, k);
                s = fmaf(xk0, ws[lane * 65 + 2 * k],     s);
                s = fmaf(xk1, ws[lane * 65 + 2 * k + 1], s);
            }
            d_gA[(size_t)i * 32 + lane] = s * dv;
        }
    }
    gbar();

    // ---- Phase 6: agg3 + relu + FC dot + mean-pool accumulation ----
    {
        int sel = d_sel32;
        const float* Wfc = (sel == 0) ? c32a : (sel == 1) ? c32b : c32c;
        const float* b3  = (sel == 0) ? c32b : c32a;
        const int is64b = !d_nz_b;
        for (int i = gw; i < n; i += TOTW) {
            int beg = d_rowptr[i], end = d_rowptr[i + 1];
            float a0 = d_gA[(size_t)i * 32 + lane], a1 = 0.f, a2 = 0.f, a3 = 0.f;
            int c = beg;
            for (; c + 8 <= end; c += 8) {
                int s0 = d_srcs[c + 0], s1 = d_srcs[c + 1];
                int s2 = d_srcs[c + 2], s3 = d_srcs[c + 3];
                int s4 = d_srcs[c + 4], s5 = d_srcs[c + 5];
                int s6 = d_srcs[c + 6], s7 = d_srcs[c + 7];
                float v0 = d_gA[(size_t)s0 * 32 + lane];
                float v1 = d_gA[(size_t)s1 * 32 + lane];
                float v2 = d_gA[(size_t)s2 * 32 + lane];
                float v3 = d_gA[(size_t)s3 * 32 + lane];
                float v4 = d_gA[(size_t)s4 * 32 + lane];
                float v5 = d_gA[(size_t)s5 * 32 + lane];
                float v6 = d_gA[(size_t)s6 * 32 + lane];
                float v7 = d_gA[(size_t)s7 * 32 + lane];
                a0 += v0 + v4; a1 += v1 + v5; a2 += v2 + v6; a3 += v3 + v7;
            }
            for (; c < end; c++)
                a0 += d_gA[(size_t)d_srcs[c] * 32 + lane];
            float acc = (a0 + a1) + (a2 + a3);
            float dv = d_dinv[i];
            float h  = fmaxf(acc * dv + b3[lane], 0.0f);
            float v  = h * Wfc[lane];
            #pragma unroll
            for (int off = 16; off > 0; off >>= 1)
                v += __shfl_xor_sync(0xffffffffu, v, off);
            if (lane == 0) {
                int gph = clampi(ld_idx(batch, i, is64b), 0, G - 1);
                atomicAdd(&d_pool[gph], v);
                atomicAdd(&d_cnt[gph], 1.0f);
            }
        }
    }
    gbar();

    // ---- Phase 7: output ----
    if (bid == 0 && tid < G)
        out[tid] = d_pool[tid] / fmaxf(d_cnt[tid], 1.0f) + bfc[0];
}

// ---------------- launcher ----------------
extern "C" void kernel_launch(void* const* d_in, const int* in_sizes, int n_in,
                              void* d_out, int out_size) {
    int ie = -1, ix = -1, ib = -1, ibfc = -1;
    int i2048[2] = {-1, -1}, n2048 = 0;
    int i64a[2]  = {-1, -1}, n64 = 0;
    int i32a[3]  = {-1, -1, -1}, n32 = 0;
    for (int i = 0; i < n_in; i++) {
        int s = in_sizes[i];
        if      (s == 3200000) ie = i;
        else if (s == 200000)  ix = i;
        else if (s == 100000)  ib = i;
        else if (s == 2048 && n2048 < 2) i2048[n2048++] = i;
        else if (s == 64   && n64   < 2) i64a[n64++]    = i;
        else if (s == 32   && n32   < 3) i32a[n32++]    = i;
        else if (s == 1)       ibfc = i;
    }
    if (ie < 0 || ix < 0 || ib < 0 || ibfc < 0 || n2048 < 2 || n64 < 2 || n32 < 3) {
        ix = 0; ie = 1; ib = 2;
        i64a[0] = 3;  i32a[0] = 4;  i2048[0] = 5; i64a[1] = 6;
        i2048[1] = 7; i32a[1] = 8;  i32a[2] = 9;  ibfc = 10;
    }

    k_all<<<NBLK, NTHR>>>((const float*)d_in[ix], d_in[ie], d_in[ib],
                          (const float*)d_in[i64a[0]], (const float*)d_in[i64a[1]],
                          (const float*)d_in[i2048[0]], (const float*)d_in[i2048[1]],
                          (const float*)d_in[i32a[0]], (const float*)d_in[i32a[1]],
                          (const float*)d_in[i32a[2]], (const float*)d_in[ibfc],
                          (float*)d_out, 100000, 1600000, out_size);
}

// round 16
// speedup vs baseline: 1.4182x; 1.4182x over previous
#include <cuda_runtime.h>
#include <cuda_fp16.h>
#include <cstdint>

// ---------------- problem constants ----------------
#define MAXN 100000
#define MAXE 1600000
#define MAXG 512
#define NBLK 444              // 3 blocks per SM (148 SMs): residency guaranteed
#define NTHR 512
#define NWARP 16
#define TOTW (NBLK * NWARP)   // 7104 warps
#define CHUNK 226             // ceil(MAXN / NBLK)

typedef long long i64;

// ---------------- static scratch (device-code references only) -------------
__device__ unsigned d_bar_arrive;
__device__ unsigned d_bar_gen;
__device__ int   d_nz_e;              // set-only: 1 => edge indices are int32
__device__ int   d_nz_b;
__device__ int   d_sel64;
__device__ int   d_sel32;
__device__ int   d_ecnt  [MAXN];
__device__ int   d_rowptr[MAXN + 1];
__device__ int   d_cursor[MAXN];
__device__ int   d_bsum  [NBLK];
__device__ int   d_bsumx [NBLK];
__device__ int   d_srcs  [MAXE];
__device__ float d_dinv  [MAXN];
__device__ __align__(128) float   d_gA [MAXN * 32];
__device__ __align__(128) __half2 d_gBh[MAXN * 32];
__device__ float d_pool[MAXG];
__device__ float d_cnt [MAXG];

// ---------------- helpers ----------------
__device__ __forceinline__ int clampi(int v, int lo, int hi) {
    return min(max(v, lo), hi);
}
__device__ __forceinline__ int ld_idx(const void* p, long long e, int is64) {
    if (is64) return (int)((const i64*)p)[e];
    return ((const int*)p)[e];
}

// Global barrier across NBLK blocks (release fence in, CCTL.IVALL out).
__device__ __forceinline__ void gbar() {
    __syncthreads();
    if (threadIdx.x == 0) {
        __threadfence();
        unsigned gen = atomicAdd(&d_bar_gen, 0u);
        unsigned a   = atomicAdd(&d_bar_arrive, 1u);
        if (a == NBLK - 1) {
            atomicExch(&d_bar_arrive, 0u);
            atomicAdd(&d_bar_gen, 1u);
        } else {
            while (atomicAdd(&d_bar_gen, 0u) == gen) __nanosleep(64);
        }
        __threadfence();
    }
    __syncthreads();
}

// ---------------- the one kernel ----------------
__global__ void __launch_bounds__(NTHR, 3)
k_all(const float* __restrict__ x, const void* __restrict__ ei,
      const void* __restrict__ batch,
      const float* c64a, const float* c64b,
      const float* __restrict__ W2, const float* __restrict__ W3,
      const float* c32a, const float* c32b, const float* c32c,
      const float* __restrict__ bfc, float* __restrict__ out,
      int n, int E, int G) {
    __shared__ float ws[64 * 33];
    __shared__ int   s_w[NWARP];

    const int tid  = threadIdx.x;
    const int lane = tid & 31;
    const int wid  = tid >> 5;
    const int bid  = blockIdx.x;
    const int gtid = bid * NTHR + tid;
    const int GS   = NBLK * NTHR;

    // ---- Phase 0: zero + width detect + weight/bias disambiguation ----
    for (int i = gtid; i < n; i += GS) d_ecnt[i] = 0;
    if (gtid < G) { d_pool[gtid] = 0.0f; d_cnt[gtid] = 0.0f; }
    if (gtid < 4096) {
        if (((const int*)ei)[2 * gtid + 1] != 0) d_nz_e = 1;
    } else if (gtid < 8192) {
        int j = gtid - 4096;
        if (((const int*)batch)[2 * j + 1] != 0) d_nz_b = 1;
    }
    if (bid == 0 && tid < 32) {
        unsigned nz64 = __ballot_sync(0xffffffffu,
                                      c64a[tid] != 0.0f || c64a[tid + 32] != 0.0f);
        unsigned nzA  = __ballot_sync(0xffffffffu, c32a[tid] != 0.0f);
        unsigned nzB  = __ballot_sync(0xffffffffu, c32b[tid] != 0.0f);
        if (tid == 0) {
            d_sel64 = nz64 ? 0 : 1;
            d_sel32 = nzA ? 0 : (nzB ? 1 : 2);
        }
    }
    gbar();

    const int is64e = !d_nz_e;

    // ---- Phase 1: in-degree histogram over dst ----
    for (int e = gtid; e < E; e += GS) {
        int d = clampi(ld_idx(ei, (long long)E + e, is64e), 0, n - 1);
        atomicAdd(&d_ecnt[d], 1);
    }
    gbar();

    // ---- Phase 2a: per-block partial sums over contiguous chunk ----
    const int cbeg = bid * CHUNK;
    const int cend = min(n, cbeg + CHUNK);
    {
        int s = 0;
        for (int i = cbeg + tid; i < cend; i += NTHR) s += d_ecnt[i];
        #pragma unroll
        for (int off = 16; off > 0; off >>= 1)
            s += __shfl_xor_sync(0xffffffffu, s, off);
        if (lane == 0) s_w[wid] = s;
        __syncthreads();
        if (wid == 0) {
            int w = (lane < NWARP) ? s_w[lane] : 0;
            #pragma unroll
            for (int off = 16; off > 0; off >>= 1)
                w += __shfl_xor_sync(0xffffffffu, w, off);
            if (lane == 0) d_bsum[bid] = w;
        }
    }
    gbar();

    // ---- Phase 2b: block 0 exclusive-scans the NBLK partials ----
    if (bid == 0) {
        int v = (tid < NBLK) ? d_bsum[tid] : 0;
        int xx = v;
        #pragma unroll
        for (int off = 1; off < 32; off <<= 1) {
            int t = __shfl_up_sync(0xffffffffu, xx, off);
            if (lane >= off) xx += t;
        }
        if (lane == 31) s_w[wid] = xx;
        __syncthreads();
        if (wid == 0) {
            int w = (lane < NWARP) ? s_w[lane] : 0;
            #pragma unroll
            for (int off = 1; off < NWARP; off <<= 1) {
                int t = __shfl_up_sync(0xffffffffu, w, off);
                if (lane >= off) w += t;
            }
            if (lane < NWARP) s_w[lane] = w;
        }
        __syncthreads();
        int incl = xx + (wid > 0 ? s_w[wid - 1] : 0);
        if (tid < NBLK) d_bsumx[tid] = incl - v;
        if (tid == NBLK - 1) d_rowptr[n] = incl;
        __syncthreads();
    }
    gbar();

    // ---- Phase 2c: local exclusive scan -> rowptr/cursor/dinv; fused L1 ----
    {
        int carry = d_bsumx[bid];
        for (int base = cbeg; base < cend; base += NTHR) {
            int i = base + tid;
            int v = (i < cend) ? d_ecnt[i] : 0;
            int xx = v;
            #pragma unroll
            for (int off = 1; off < 32; off <<= 1) {
                int t = __shfl_up_sync(0xffffffffu, xx, off);
                if (lane >= off) xx += t;
            }
            if (lane == 31) s_w[wid] = xx;
            __syncthreads();
            if (wid == 0) {
                int w = (lane < NWARP) ? s_w[lane] : 0;
                #pragma unroll
                for (int off = 1; off < NWARP; off <<= 1) {
                    int t = __shfl_up_sync(0xffffffffu, w, off);
                    if (lane >= off) w += t;
                }
                if (lane < NWARP) s_w[lane] = w;
            }
            __syncthreads();
            int incl = xx + (wid > 0 ? s_w[wid - 1] : 0);
            int btot = s_w[NWARP - 1];
            if (i < cend) {
                int pre = carry + incl - v;
                d_rowptr[i] = pre;
                d_cursor[i] = pre;
                d_dinv[i]   = rsqrtf(1.0f + (float)v);
            }
            carry += btot;
            __syncthreads();
        }
        const float* W1 = (d_sel64 == 0) ? c64a : c64b;
        int cnt = cend - cbeg;
        for (int t = tid; t < cnt * 32; t += NTHR) {
            int node = cbeg + (t >> 5);
            int f = t & 31;
            float h = W1[f * 2 + 0] * x[node * 2 + 0]
                    + W1[f * 2 + 1] * x[node * 2 + 1];
            d_gA[(size_t)node * 32 + f] = h * d_dinv[node];
        }
    }
    gbar();

    // ---- Phase 3: CSR placement ----
    for (int e = gtid; e < E; e += GS) {
        int s = clampi(ld_idx(ei, e, is64e),                0, n - 1);
        int d = clampi(ld_idx(ei, (long long)E + e, is64e), 0, n - 1);
        int pos = atomicAdd(&d_cursor[d], 1);
        d_srcs[pos] = s;
    }
    gbar();

    const int gw = bid * NWARP + wid;

    // ---- Phase 4: agg1 = Agg(g1)+relu+GEMV W2 -> gBh (half2 pairs) ----
    for (int t = tid; t < 64 * 32; t += NTHR)
        ws[(t >> 5) * 33 + (t & 31)] = W2[t];
    __syncthreads();
    {
        const float* b1 = (d_sel32 == 0) ? c32b : c32a;
        for (int i = gw; i < n; i += TOTW) {
            int beg = d_rowptr[i], end = d_rowptr[i + 1];
            float a0 = d_gA[(size_t)i * 32 + lane], a1 = 0.f, a2 = 0.f, a3 = 0.f;
            int c = beg;
            for (; c + 8 <= end; c += 8) {
                int s0 = d_srcs[c + 0], s1 = d_srcs[c + 1];
                int s2 = d_srcs[c + 2], s3 = d_srcs[c + 3];
                int s4 = d_srcs[c + 4], s5 = d_srcs[c + 5];
                int s6 = d_srcs[c + 6], s7 = d_srcs[c + 7];
                float v0 = d_gA[(size_t)s0 * 32 + lane];
                float v1 = d_gA[(size_t)s1 * 32 + lane];
                float v2 = d_gA[(size_t)s2 * 32 + lane];
                float v3 = d_gA[(size_t)s3 * 32 + lane];
                float v4 = d_gA[(size_t)s4 * 32 + lane];
                float v5 = d_gA[(size_t)s5 * 32 + lane];
                float v6 = d_gA[(size_t)s6 * 32 + lane];
                float v7 = d_gA[(size_t)s7 * 32 + lane];
                a0 += v0 + v4; a1 += v1 + v5; a2 += v2 + v6; a3 += v3 + v7;
            }
            for (; c < end; c++)
                a0 += d_gA[(size_t)d_srcs[c] * 32 + lane];
            float acc = (a0 + a1) + (a2 + a3);
            float dv = d_dinv[i];
            float xi = fmaxf(acc * dv + b1[lane], 0.0f);
            float s0 = 0.0f, s1 = 0.0f;
            #pragma unroll
            for (int k = 0; k < 32; k++) {
                float xk = __shfl_sync(0xffffffffu, xi, k);
                s0 = fmaf(xk, ws[(2 * lane)     * 33 + k], s0);
                s1 = fmaf(xk, ws[(2 * lane + 1) * 33 + k], s1);
            }
            d_gBh[(size_t)i * 32 + lane] = __floats2half2_rn(s0 * dv, s1 * dv);
        }
    }
    gbar();

    // ---- Phase 5: agg2 = Agg(gBh)+relu+GEMV W3 -> gA ----
    for (int t = tid; t < 32 * 64; t += NTHR)
        ws[(t >> 6) * 65 + (t & 63)] = W3[t];
    __syncthreads();
    {
        const float* b2 = (d_sel64 == 0) ? c64b : c64a;
        for (int i = gw; i < n; i += TOTW) {
            float2 self = __half22float2(d_gBh[(size_t)i * 32 + lane]);
            float a0 = self.x, a1 = self.y, a2 = 0.f, a3 = 0.f;
            int beg = d_rowptr[i], end = d_rowptr[i + 1];
            int c = beg;
            for (; c + 8 <= end; c += 8) {
                int s0 = d_srcs[c + 0], s1 = d_srcs[c + 1];
                int s2 = d_srcs[c + 2], s3 = d_srcs[c + 3];
                int s4 = d_srcs[c + 4], s5 = d_srcs[c + 5];
                int s6 = d_srcs[c + 6], s7 = d_srcs[c + 7];
                float2 v0 = __half22float2(d_gBh[(size_t)s0 * 32 + lane]);
                float2 v1 = __half22float2(d_gBh[(size_t)s1 * 32 + lane]);
                float2 v2 = __half22float2(d_gBh[(size_t)s2 * 32 + lane]);
                float2 v3 = __half22float2(d_gBh[(size_t)s3 * 32 + lane]);
                float2 v4 = __half22float2(d_gBh[(size_t)s4 * 32 + lane]);
                float2 v5 = __half22float2(d_gBh[(size_t)s5 * 32 + lane]);
                float2 v6 = __half22float2(d_gBh[(size_t)s6 * 32 + lane]);
                float2 v7 = __half22float2(d_gBh[(size_t)s7 * 32 + lane]);
                a0 += v0.x + v4.x; a1 += v0.y + v4.y;
                a2 += v1.x + v5.x; a3 += v1.y + v5.y;
                a0 += v2.x + v6.x; a1 += v2.y + v6.y;
                a2 += v3.x + v7.x; a3 += v3.y + v7.y;
            }
            for (; c < end; c++) {
                float2 v = __half22float2(d_gBh[(size_t)d_srcs[c] * 32 + lane]);
                a0 += v.x; a1 += v.y;
            }
            float acc0 = a0 + a2, acc1 = a1 + a3;
            float dv = d_dinv[i];
            float xe = fmaxf(acc0 * dv + b2[2 * lane],     0.0f);
            float xo = fmaxf(acc1 * dv + b2[2 * lane + 1], 0.0f);
            float s = 0.0f;
            #pragma unroll
            for (int k = 0; k < 32; k++) {
                float xk0 = __shfl_sync(0xffffffffu, xe, k);
                float xk1 = __shfl_sync(0xffffffffu, xo, k);
                s = fmaf(xk0, ws[lane * 65 + 2 * k],     s);
                s = fmaf(xk1, ws[lane * 65 + 2 * k + 1], s);
            }
            d_gA[(size_t)i * 32 + lane] = s * dv;
        }
    }
    gbar();

    // ---- Phase 6: agg3 + relu + FC dot + mean-pool accumulation ----
    {
        int sel = d_sel32;
        const float* Wfc = (sel == 0) ? c32a : (sel == 1) ? c32b : c32c;
        const float* b3  = (sel == 0) ? c32b : c32a;
        const int is64b = !d_nz_b;
        for (int i = gw; i < n; i += TOTW) {
            int beg = d_rowptr[i], end = d_rowptr[i + 1];
            float a0 = d_gA[(size_t)i * 32 + lane], a1 = 0.f, a2 = 0.f, a3 = 0.f;
            int c = beg;
            for (; c + 8 <= end; c += 8) {
                int s0 = d_srcs[c + 0], s1 = d_srcs[c + 1];
                int s2 = d_srcs[c + 2], s3 = d_srcs[c + 3];
                int s4 = d_srcs[c + 4], s5 = d_srcs[c + 5];
                int s6 = d_srcs[c + 6], s7 = d_srcs[c + 7];
                float v0 = d_gA[(size_t)s0 * 32 + lane];
                float v1 = d_gA[(size_t)s1 * 32 + lane];
                float v2 = d_gA[(size_t)s2 * 32 + lane];
                float v3 = d_gA[(size_t)s3 * 32 + lane];
                float v4 = d_gA[(size_t)s4 * 32 + lane];
                float v5 = d_gA[(size_t)s5 * 32 + lane];
                float v6 = d_gA[(size_t)s6 * 32 + lane];
                float v7 = d_gA[(size_t)s7 * 32 + lane];
                a0 += v0 + v4; a1 += v1 + v5; a2 += v2 + v6; a3 += v3 + v7;
            }
            for (; c < end; c++)
                a0 += d_gA[(size_t)d_srcs[c] * 32 + lane];
            float acc = (a0 + a1) + (a2 + a3);
            float dv = d_dinv[i];
            float h  = fmaxf(acc * dv + b3[lane], 0.0f);
            float v  = h * Wfc[lane];
            #pragma unroll
            for (int off = 16; off > 0; off >>= 1)
                v += __shfl_xor_sync(0xffffffffu, v, off);
            if (lane == 0) {
                int gph = clampi(ld_idx(batch, i, is64b), 0, G - 1);
                atomicAdd(&d_pool[gph], v);
                atomicAdd(&d_cnt[gph], 1.0f);
            }
        }
    }
    gbar();

    // ---- Phase 7: output ----
    if (bid == 0 && tid < G)
        out[tid] = d_pool[tid] / fmaxf(d_cnt[tid], 1.0f) + bfc[0];
}

// ---------------- launcher ----------------
extern "C" void kernel_launch(void* const* d_in, const int* in_sizes, int n_in,
                              void* d_out, int out_size) {
    int ie = -1, ix = -1, ib = -1, ibfc = -1;
    int i2048[2] = {-1, -1}, n2048 = 0;
    int i64a[2]  = {-1, -1}, n64 = 0;
    int i32a[3]  = {-1, -1, -1}, n32 = 0;
    for (int i = 0; i < n_in; i++) {
        int s = in_sizes[i];
        if      (s == 3200000) ie = i;
        else if (s == 200000)  ix = i;
        else if (s == 100000)  ib = i;
        else if (s == 2048 && n2048 < 2) i2048[n2048++] = i;
        else if (s == 64   && n64   < 2) i64a[n64++]    = i;
        else if (s == 32   && n32   < 3) i32a[n32++]    = i;
        else if (s == 1)       ibfc = i;
    }
    if (ie < 0 || ix < 0 || ib < 0 || ibfc < 0 || n2048 < 2 || n64 < 2 || n32 < 3) {
        ix = 0; ie = 1; ib = 2;
        i64a[0] = 3;  i32a[0] = 4;  i2048[0] = 5; i64a[1] = 6;
        i2048[1] = 7; i32a[1] = 8;  i32a[2] = 9;  ibfc = 10;
    }

    k_all<<<NBLK, NTHR>>>((const float*)d_in[ix], d_in[ie], d_in[ib],
                          (const float*)d_in[i64a[0]], (const float*)d_in[i64a[1]],
                          (const float*)d_in[i2048[0]], (const float*)d_in[i2048[1]],
                          (const float*)d_in[i32a[0]], (const float*)d_in[i32a[1]],
                          (const float*)d_in[i32a[2]], (const float*)d_in[ibfc],
                          (float*)d_out, 100000, 1600000, out_size);
}

// round 17
// speedup vs baseline: 1.4222x; 1.0028x over previous
#include <cuda_runtime.h>
#include <cuda_fp16.h>
#include <cstdint>

// ---------------- problem constants ----------------
#define MAXN 100000
#define MAXE 1600000
#define MAXG 512
#define NBLK 444              // 3 blocks per SM (148 SMs): residency guaranteed
#define NTHR 512
#define NWARP 16
#define TOTW (NBLK * NWARP)   // 7104 warps
#define CHUNK 226             // ceil(MAXN / NBLK)

typedef long long i64;

// ---------------- static scratch (device-code references only) -------------
__device__ unsigned d_bar_arrive;
__device__ unsigned d_bar_gen;
__device__ int   d_nz_e;              // set-only: 1 => edge indices are int32
__device__ int   d_nz_b;
__device__ int   d_sel64;
__device__ int   d_sel32;
__device__ int   d_ecnt  [MAXN];
__device__ int   d_rowptr[MAXN + 1];
__device__ int   d_cursor[MAXN];
__device__ int   d_bsum  [NBLK];
__device__ int   d_bsumx [NBLK];
__device__ int   d_srcs  [MAXE];
__device__ float d_dinv  [MAXN];
__device__ __align__(128) float   d_gA [MAXN * 32];
__device__ __align__(128) __half2 d_gBh[MAXN * 32];
__device__ float d_pool[MAXG];
__device__ float d_cnt [MAXG];

// ---------------- helpers ----------------
__device__ __forceinline__ int clampi(int v, int lo, int hi) {
    return min(max(v, lo), hi);
}
__device__ __forceinline__ int ld_idx(const void* p, long long e, int is64) {
    if (is64) return (int)((const i64*)p)[e];
    return ((const int*)p)[e];
}

// Global barrier across NBLK blocks (release fence in, CCTL.IVALL out).
__device__ __forceinline__ void gbar() {
    __syncthreads();
    if (threadIdx.x == 0) {
        __threadfence();
        unsigned gen = atomicAdd(&d_bar_gen, 0u);
        unsigned a   = atomicAdd(&d_bar_arrive, 1u);
        if (a == NBLK - 1) {
            atomicExch(&d_bar_arrive, 0u);
            atomicAdd(&d_bar_gen, 1u);
        } else {
            while (atomicAdd(&d_bar_gen, 0u) == gen) __nanosleep(64);
        }
        __threadfence();
    }
    __syncthreads();
}

// ---------------- the one kernel ----------------
__global__ void __launch_bounds__(NTHR, 3)
k_all(const float* __restrict__ x, const void* __restrict__ ei,
      const void* __restrict__ batch,
      const float* c64a, const float* c64b,
      const float* __restrict__ W2, const float* __restrict__ W3,
      const float* c32a, const float* c32b, const float* c32c,
      const float* __restrict__ bfc, float* __restrict__ out,
      int n, int E, int G) {
    __shared__ float ws[64 * 33];
    __shared__ int   s_w[NWARP];

    const int tid  = threadIdx.x;
    const int lane = tid & 31;
    const int wid  = tid >> 5;
    const int bid  = blockIdx.x;
    const int gtid = bid * NTHR + tid;
    const int GS   = NBLK * NTHR;

    // ---- Phase 0: zero + width detect + weight/bias disambiguation ----
    for (int i = gtid; i < n; i += GS) d_ecnt[i] = 0;
    if (gtid < G) { d_pool[gtid] = 0.0f; d_cnt[gtid] = 0.0f; }
    if (gtid < 4096) {
        if (((const int*)ei)[2 * gtid + 1] != 0) d_nz_e = 1;
    } else if (gtid < 8192) {
        int j = gtid - 4096;
        if (((const int*)batch)[2 * j + 1] != 0) d_nz_b = 1;
    }
    if (bid == 0 && tid < 32) {
        unsigned nz64 = __ballot_sync(0xffffffffu,
                                      c64a[tid] != 0.0f || c64a[tid + 32] != 0.0f);
        unsigned nzA  = __ballot_sync(0xffffffffu, c32a[tid] != 0.0f);
        unsigned nzB  = __ballot_sync(0xffffffffu, c32b[tid] != 0.0f);
        if (tid == 0) {
            d_sel64 = nz64 ? 0 : 1;
            d_sel32 = nzA ? 0 : (nzB ? 1 : 2);
        }
    }
    gbar();

    const int is64e = !d_nz_e;

    // ---- Phase 1: in-degree histogram over dst ----
    for (int e = gtid; e < E; e += GS) {
        int d = clampi(ld_idx(ei, (long long)E + e, is64e), 0, n - 1);
        atomicAdd(&d_ecnt[d], 1);
    }
    gbar();

    // ---- Phase 2a: per-block partial sums over contiguous chunk ----
    const int cbeg = bid * CHUNK;
    const int cend = min(n, cbeg + CHUNK);
    {
        int s = 0;
        for (int i = cbeg + tid; i < cend; i += NTHR) s += d_ecnt[i];
        #pragma unroll
        for (int off = 16; off > 0; off >>= 1)
            s += __shfl_xor_sync(0xffffffffu, s, off);
        if (lane == 0) s_w[wid] = s;
        __syncthreads();
        if (wid == 0) {
            int w = (lane < NWARP) ? s_w[lane] : 0;
            #pragma unroll
            for (int off = 16; off > 0; off >>= 1)
                w += __shfl_xor_sync(0xffffffffu, w, off);
            if (lane == 0) d_bsum[bid] = w;
        }
    }
    gbar();

    // ---- Phase 2b: block 0 exclusive-scans the NBLK partials ----
    if (bid == 0) {
        int v = (tid < NBLK) ? d_bsum[tid] : 0;
        int xx = v;
        #pragma unroll
        for (int off = 1; off < 32; off <<= 1) {
            int t = __shfl_up_sync(0xffffffffu, xx, off);
            if (lane >= off) xx += t;
        }
        if (lane == 31) s_w[wid] = xx;
        __syncthreads();
        if (wid == 0) {
            int w = (lane < NWARP) ? s_w[lane] : 0;
            #pragma unroll
            for (int off = 1; off < NWARP; off <<= 1) {
                int t = __shfl_up_sync(0xffffffffu, w, off);
                if (lane >= off) w += t;
            }
            if (lane < NWARP) s_w[lane] = w;
        }
        __syncthreads();
        int incl = xx + (wid > 0 ? s_w[wid - 1] : 0);
        if (tid < NBLK) d_bsumx[tid] = incl - v;
        if (tid == NBLK - 1) d_rowptr[n] = incl;
        __syncthreads();
    }
    gbar();

    // ---- Phase 2c: local exclusive scan -> rowptr/cursor/dinv; fused L1 ----
    {
        int carry = d_bsumx[bid];
        for (int base = cbeg; base < cend; base += NTHR) {
            int i = base + tid;
            int v = (i < cend) ? d_ecnt[i] : 0;
            int xx = v;
            #pragma unroll
            for (int off = 1; off < 32; off <<= 1) {
                int t = __shfl_up_sync(0xffffffffu, xx, off);
                if (lane >= off) xx += t;
            }
            if (lane == 31) s_w[wid] = xx;
            __syncthreads();
            if (wid == 0) {
                int w = (lane < NWARP) ? s_w[lane] : 0;
                #pragma unroll
                for (int off = 1; off < NWARP; off <<= 1) {
                    int t = __shfl_up_sync(0xffffffffu, w, off);
                    if (lane >= off) w += t;
                }
                if (lane < NWARP) s_w[lane] = w;
            }
            __syncthreads();
            int incl = xx + (wid > 0 ? s_w[wid - 1] : 0);
            int btot = s_w[NWARP - 1];
            if (i < cend) {
                int pre = carry + incl - v;
                d_rowptr[i] = pre;
                d_cursor[i] = pre;
                d_dinv[i]   = rsqrtf(1.0f + (float)v);
            }
            carry += btot;
            __syncthreads();
        }
        const float* W1 = (d_sel64 == 0) ? c64a : c64b;
        int cnt = cend - cbeg;
        for (int t = tid; t < cnt * 32; t += NTHR) {
            int node = cbeg + (t >> 5);
            int f = t & 31;
            float h = W1[f * 2 + 0] * x[node * 2 + 0]
                    + W1[f * 2 + 1] * x[node * 2 + 1];
            d_gA[(size_t)node * 32 + f] = h * d_dinv[node];
        }
    }
    gbar();

    // ---- Phase 3: CSR placement ----
    for (int e = gtid; e < E; e += GS) {
        int s = clampi(ld_idx(ei, e, is64e),                0, n - 1);
        int d = clampi(ld_idx(ei, (long long)E + e, is64e), 0, n - 1);
        int pos = atomicAdd(&d_cursor[d], 1);
        d_srcs[pos] = s;
    }
    gbar();

    const int gw = bid * NWARP + wid;

    // ---- Phase 4: agg1 = Agg(g1)+relu+GEMV W2 -> gBh (half2 pairs) ----
    for (int t = tid; t < 64 * 32; t += NTHR)
        ws[(t >> 5) * 33 + (t & 31)] = W2[t];
    __syncthreads();
    {
        const float* b1 = (d_sel32 == 0) ? c32b : c32a;
        for (int i = gw; i < n; i += TOTW) {
            int beg = d_rowptr[i], end = d_rowptr[i + 1];
            float a0 = d_gA[(size_t)i * 32 + lane], a1 = 0.f, a2 = 0.f, a3 = 0.f;
            int c = beg;
            for (; c + 8 <= end; c += 8) {
                int s0 = d_srcs[c + 0], s1 = d_srcs[c + 1];
                int s2 = d_srcs[c + 2], s3 = d_srcs[c + 3];
                int s4 = d_srcs[c + 4], s5 = d_srcs[c + 5];
                int s6 = d_srcs[c + 6], s7 = d_srcs[c + 7];
                float v0 = d_gA[(size_t)s0 * 32 + lane];
                float v1 = d_gA[(size_t)s1 * 32 + lane];
                float v2 = d_gA[(size_t)s2 * 32 + lane];
                float v3 = d_gA[(size_t)s3 * 32 + lane];
                float v4 = d_gA[(size_t)s4 * 32 + lane];
                float v5 = d_gA[(size_t)s5 * 32 + lane];
                float v6 = d_gA[(size_t)s6 * 32 + lane];
                float v7 = d_gA[(size_t)s7 * 32 + lane];
                a0 += v0 + v4; a1 += v1 + v5; a2 += v2 + v6; a3 += v3 + v7;
            }
            for (; c < end; c++)
                a0 += d_gA[(size_t)d_srcs[c] * 32 + lane];
            float acc = (a0 + a1) + (a2 + a3);
            float dv = d_dinv[i];
            float xi = fmaxf(acc * dv + b1[lane], 0.0f);
            float s0 = 0.0f, s1 = 0.0f;
            #pragma unroll
            for (int k = 0; k < 32; k++) {
                float xk = __shfl_sync(0xffffffffu, xi, k);
                s0 = fmaf(xk, ws[(2 * lane)     * 33 + k], s0);
                s1 = fmaf(xk, ws[(2 * lane + 1) * 33 + k], s1);
            }
            d_gBh[(size_t)i * 32 + lane] = __floats2half2_rn(s0 * dv, s1 * dv);
        }
    }
    gbar();

    // ---- Phase 5: agg2 = Agg(gBh)+relu+GEMV W3 -> gA ----
    for (int t = tid; t < 32 * 64; t += NTHR)
        ws[(t >> 6) * 65 + (t & 63)] = W3[t];
    __syncthreads();
    {
        const float* b2 = (d_sel64 == 0) ? c64b : c64a;
        for (int i = gw; i < n; i += TOTW) {
            float2 self = __half22float2(d_gBh[(size_t)i * 32 + lane]);
            float a0 = self.x, a1 = self.y, a2 = 0.f, a3 = 0.f;
            int beg = d_rowptr[i], end = d_rowptr[i + 1];
            int c = beg;
            for (; c + 8 <= end; c += 8) {
                int s0 = d_srcs[c + 0], s1 = d_srcs[c + 1];
                int s2 = d_srcs[c + 2], s3 = d_srcs[c + 3];
                int s4 = d_srcs[c + 4], s5 = d_srcs[c + 5];
                int s6 = d_srcs[c + 6], s7 = d_srcs[c + 7];
                float2 v0 = __half22float2(d_gBh[(size_t)s0 * 32 + lane]);
                float2 v1 = __half22float2(d_gBh[(size_t)s1 * 32 + lane]);
                float2 v2 = __half22float2(d_gBh[(size_t)s2 * 32 + lane]);
                float2 v3 = __half22float2(d_gBh[(size_t)s3 * 32 + lane]);
                float2 v4 = __half22float2(d_gBh[(size_t)s4 * 32 + lane]);
                float2 v5 = __half22float2(d_gBh[(size_t)s5 * 32 + lane]);
                float2 v6 = __half22float2(d_gBh[(size_t)s6 * 32 + lane]);
                float2 v7 = __half22float2(d_gBh[(size_t)s7 * 32 + lane]);
                a0 += v0.x + v4.x; a1 += v0.y + v4.y;
                a2 += v1.x + v5.x; a3 += v1.y + v5.y;
                a0 += v2.x + v6.x; a1 += v2.y + v6.y;
                a2 += v3.x + v7.x; a3 += v3.y + v7.y;
            }
            for (; c < end; c++) {
                float2 v = __half22float2(d_gBh[(size_t)d_srcs[c] * 32 + lane]);
                a0 += v.x; a1 += v.y;
            }
            float acc0 = a0 + a2, acc1 = a1 + a3;
            float dv = d_dinv[i];
            float xe = fmaxf(acc0 * dv + b2[2 * lane],     0.0f);
            float xo = fmaxf(acc1 * dv + b2[2 * lane + 1], 0.0f);
            float s = 0.0f;
            #pragma unroll
            for (int k = 0; k < 32; k++) {
                float xk0 = __shfl_sync(0xffffffffu, xe, k);
                float xk1 = __shfl_sync(0xffffffffu, xo, k);
                s = fmaf(xk0, ws[lane * 65 + 2 * k],     s);
                s = fmaf(xk1, ws[lane * 65 + 2 * k + 1], s);
            }
            d_gA[(size_t)i * 32 + lane] = s * dv;
        }
    }
    gbar();

    // ---- Phase 6: agg3 + relu + FC dot + mean-pool accumulation ----
    {
        int sel = d_sel32;
        const float* Wfc = (sel == 0) ? c32a : (sel == 1) ? c32b : c32c;
        const float* b3  = (sel == 0) ? c32b : c32a;
        const int is64b = !d_nz_b;
        for (int i = gw; i < n; i += TOTW) {
            int beg = d_rowptr[i], end = d_rowptr[i + 1];
            float a0 = d_gA[(size_t)i * 32 + lane], a1 = 0.f, a2 = 0.f, a3 = 0.f;
            int c = beg;
            for (; c + 8 <= end; c += 8) {
                int s0 = d_srcs[c + 0], s1 = d_srcs[c + 1];
                int s2 = d_srcs[c + 2], s3 = d_srcs[c + 3];
                int s4 = d_srcs[c + 4], s5 = d_srcs[c + 5];
                int s6 = d_srcs[c + 6], s7 = d_srcs[c + 7];
                float v0 = d_gA[(size_t)s0 * 32 + lane];
                float v1 = d_gA[(size_t)s1 * 32 + lane];
                float v2 = d_gA[(size_t)s2 * 32 + lane];
                float v3 = d_gA[(size_t)s3 * 32 + lane];
                float v4 = d_gA[(size_t)s4 * 32 + lane];
                float v5 = d_gA[(size_t)s5 * 32 + lane];
                float v6 = d_gA[(size_t)s6 * 32 + lane];
                float v7 = d_gA[(size_t)s7 * 32 + lane];
                a0 += v0 + v4; a1 += v1 + v5; a2 += v2 + v6; a3 += v3 + v7;
            }
            for (; c < end; c++)
                a0 += d_gA[(size_t)d_srcs[c] * 32 + lane];
            float acc = (a0 + a1) + (a2 + a3);
            float dv = d_dinv[i];
            float h  = fmaxf(acc * dv + b3[lane], 0.0f);
            float v  = h * Wfc[lane];
            #pragma unroll
            for (int off = 16; off > 0; off >>= 1)
                v += __shfl_xor_sync(0xffffffffu, v, off);
            if (lane == 0) {
                int gph = clampi(ld_idx(batch, i, is64b), 0, G - 1);
                atomicAdd(&d_pool[gph], v);
                atomicAdd(&d_cnt[gph], 1.0f);
            }
        }
    }
    gbar();

    // ---- Phase 7: output ----
    if (bid == 0 && tid < G)
        out[tid] = d_pool[tid] / fmaxf(d_cnt[tid], 1.0f) + bfc[0];
}

// ---------------- launcher ----------------
extern "C" void kernel_launch(void* const* d_in, const int* in_sizes, int n_in,
                              void* d_out, int out_size) {
    int ie = -1, ix = -1, ib = -1, ibfc = -1;
    int i2048[2] = {-1, -1}, n2048 = 0;
    int i64a[2]  = {-1, -1}, n64 = 0;
    int i32a[3]  = {-1, -1, -1}, n32 = 0;
    for (int i = 0; i < n_in; i++) {
        int s = in_sizes[i];
        if      (s == 3200000) ie = i;
        else if (s == 200000)  ix = i;
        else if (s == 100000)  ib = i;
        else if (s == 2048 && n2048 < 2) i2048[n2048++] = i;
        else if (s == 64   && n64   < 2) i64a[n64++]    = i;
        else if (s == 32   && n32   < 3) i32a[n32++]    = i;
        else if (s == 1)       ibfc = i;
    }
    if (ie < 0 || ix < 0 || ib < 0 || ibfc < 0 || n2048 < 2 || n64 < 2 || n32 < 3) {
        ix = 0; ie = 1; ib = 2;
        i64a[0] = 3;  i32a[0] = 4;  i2048[0] = 5; i64a[1] = 6;
        i2048[1] = 7; i32a[1] = 8;  i32a[2] = 9;  ibfc = 10;
    }

    k_all<<<NBLK, NTHR>>>((const float*)d_in[ix], d_in[ie], d_in[ib],
                          (const float*)d_in[i64a[0]], (const float*)d_in[i64a[1]],
                          (const float*)d_in[i2048[0]], (const float*)d_in[i2048[1]],
                          (const float*)d_in[i32a[0]], (const float*)d_in[i32a[1]],
                          (const float*)d_in[i32a[2]], (const float*)d_in[ibfc],
                          (float*)d_out, 100000, 1600000, out_size);
}